// round 1
// baseline (speedup 1.0000x reference)
#include <cuda_runtime.h>

#define B_TOT 32768

typedef unsigned long long ull;

// ---------------- scratch (static device allocations) ----------------
__device__ float g_v[(size_t)B_TOT * 128];        // speed embedding  [B,128]
__device__ float g_joined[(size_t)B_TOT * 512];   // joined features  [B,512]
__device__ int   g_idx[B_TOT + 256];              // bucketed sample indices (64-aligned segments)
__device__ int   g_cnt[4];
__device__ int   g_fill[4];
__device__ int   g_seg[5];

// ---------------- f32x2 packed-math helpers ----------------
#define FMA2(c, a, b) asm("fma.rn.f32x2 %0, %1, %2, %0;" : "+l"(c) : "l"(a), "l"(b))
#define PACKDUP(p, x) asm("mov.b64 %0, {%1, %1};" : "=l"(p) : "f"(x))
#define UNPK(lo, hi, p) asm("mov.b64 {%0, %1}, %2;" : "=f"(lo), "=f"(hi) : "l"(p))

// =====================================================================
// Block GEMM microkernel: Y[64 x 128] = act(Xs[64 x K] @ W[K x (cols wcol0..wcol0+127)] + bias)
//   Xs   : shared, row-major, leading dim ldx
//   W    : global, row-major, leading dim ldw
//   bias : global (indexed bias[wcol0 + n])
//   Yout : float* (shared OR global), leading dim ldy, row offset rowoff, col offset ycol0
//   Ws   : shared staging buffer, 32*128 floats
// 256 threads: tx = tid&15 (8 cols each), ty = tid>>4 (4 rows each).
// =====================================================================
template <bool RELU>
__device__ __forceinline__ void gemm64x128(
    const float* __restrict__ Xs, int ldx, int K,
    const float* __restrict__ W, int ldw, int wcol0,
    const float* __restrict__ bias,
    float* __restrict__ Yout, int ldy, size_t rowoff, int ycol0,
    float* __restrict__ Ws)
{
    const int tid = threadIdx.x;
    const int tx = tid & 15;
    const int ty = tid >> 4;

    // init accumulators with bias pairs
    ull acc[4][4];
    {
        const ull* bp = (const ull*)(bias + wcol0 + tx * 8);
        ull b0 = bp[0], b1 = bp[1], b2 = bp[2], b3 = bp[3];
#pragma unroll
        for (int i = 0; i < 4; i++) {
            acc[i][0] = b0; acc[i][1] = b1; acc[i][2] = b2; acc[i][3] = b3;
        }
    }

    const int kk0 = tid >> 3;          // 0..31 : chunk row this thread stages
    const int cs  = (tid & 7) << 4;    // 0..112: col segment (16 floats)

    const float* xr0 = Xs + (size_t)(ty * 4 + 0) * ldx;
    const float* xr1 = Xs + (size_t)(ty * 4 + 1) * ldx;
    const float* xr2 = Xs + (size_t)(ty * 4 + 2) * ldx;
    const float* xr3 = Xs + (size_t)(ty * 4 + 3) * ldx;

    // prefetch chunk 0
    float4 p0, p1, p2, p3;
    {
        const float* wp = W + (size_t)kk0 * ldw + wcol0 + cs;
        p0 = *(const float4*)(wp + 0);
        p1 = *(const float4*)(wp + 4);
        p2 = *(const float4*)(wp + 8);
        p3 = *(const float4*)(wp + 12);
    }

    const int nk = K >> 5;
    for (int c = 0; c < nk; c++) {
        {
            float4* wst = (float4*)(Ws + kk0 * 128 + cs);
            wst[0] = p0; wst[1] = p1; wst[2] = p2; wst[3] = p3;
        }
        __syncthreads();
        if (c + 1 < nk) {
            const float* wp = W + (size_t)((c + 1) * 32 + kk0) * ldw + wcol0 + cs;
            p0 = *(const float4*)(wp + 0);
            p1 = *(const float4*)(wp + 4);
            p2 = *(const float4*)(wp + 8);
            p3 = *(const float4*)(wp + 12);
        }
        const int kb = c << 5;
#pragma unroll
        for (int kk = 0; kk < 32; kk++) {
            const ulonglong2* bq = (const ulonglong2*)(Ws + kk * 128 + tx * 8);
            ulonglong2 bA = bq[0];
            ulonglong2 bB = bq[1];
            float a0 = xr0[kb + kk];
            float a1 = xr1[kb + kk];
            float a2 = xr2[kb + kk];
            float a3 = xr3[kb + kk];
            ull d0, d1, d2, d3;
            PACKDUP(d0, a0); PACKDUP(d1, a1); PACKDUP(d2, a2); PACKDUP(d3, a3);
            FMA2(acc[0][0], d0, bA.x); FMA2(acc[0][1], d0, bA.y);
            FMA2(acc[0][2], d0, bB.x); FMA2(acc[0][3], d0, bB.y);
            FMA2(acc[1][0], d1, bA.x); FMA2(acc[1][1], d1, bA.y);
            FMA2(acc[1][2], d1, bB.x); FMA2(acc[1][3], d1, bB.y);
            FMA2(acc[2][0], d2, bA.x); FMA2(acc[2][1], d2, bA.y);
            FMA2(acc[2][2], d2, bB.x); FMA2(acc[2][3], d2, bB.y);
            FMA2(acc[3][0], d3, bA.x); FMA2(acc[3][1], d3, bA.y);
            FMA2(acc[3][2], d3, bB.x); FMA2(acc[3][3], d3, bB.y);
        }
        __syncthreads();
    }

    // epilogue
#pragma unroll
    for (int i = 0; i < 4; i++) {
        float v0, v1, v2, v3, v4, v5, v6, v7;
        UNPK(v0, v1, acc[i][0]);
        UNPK(v2, v3, acc[i][1]);
        UNPK(v4, v5, acc[i][2]);
        UNPK(v6, v7, acc[i][3]);
        if (RELU) {
            v0 = fmaxf(v0, 0.f); v1 = fmaxf(v1, 0.f);
            v2 = fmaxf(v2, 0.f); v3 = fmaxf(v3, 0.f);
            v4 = fmaxf(v4, 0.f); v5 = fmaxf(v5, 0.f);
            v6 = fmaxf(v6, 0.f); v7 = fmaxf(v7, 0.f);
        }
        float4* dst = (float4*)(Yout + (rowoff + (size_t)(ty * 4 + i)) * (size_t)ldy + ycol0 + tx * 8);
        dst[0] = make_float4(v0, v1, v2, v3);
        dst[1] = make_float4(v4, v5, v6, v7);
    }
}

// ---------------- routing (bucket by command) ----------------
__global__ void k_reset() {
    int t = threadIdx.x;
    if (t < 4) { g_cnt[t] = 0; g_fill[t] = 0; }
}
__global__ void k_count(const int* __restrict__ cmd) {
    int i = blockIdx.x * 256 + threadIdx.x;
    if (i < B_TOT) atomicAdd(&g_cnt[cmd[i] & 3], 1);
}
__global__ void k_seg() {
    if (threadIdx.x == 0) {
        int off = 0;
        for (int e = 0; e < 4; e++) {
            g_seg[e] = off;
            off += (g_cnt[e] + 63) & ~63;   // 64-aligned segments
        }
        g_seg[4] = off;
    }
}
__global__ void k_scatter(const int* __restrict__ cmd) {
    int i = blockIdx.x * 256 + threadIdx.x;
    if (i < B_TOT) {
        int e = cmd[i] & 3;
        int pos = g_seg[e] + atomicAdd(&g_fill[e], 1);
        g_idx[pos] = i;
    }
}

// ---------------- speed MLP: 1 -> 128 -> 128 -> 128 ----------------
// smem: h1[64][132], h2[64][132], Ws[32*128], ss[64]
__global__ void k_sp(const float* __restrict__ speed,
                     const float* __restrict__ W1, const float* __restrict__ b1,
                     const float* __restrict__ W2, const float* __restrict__ b2,
                     const float* __restrict__ W3, const float* __restrict__ b3)
{
    extern __shared__ float sm[];
    float* h1 = sm;                   // 64*132
    float* h2 = h1 + 64 * 132;        // 64*132
    float* Ws = h2 + 64 * 132;        // 32*128
    float* ss = Ws + 32 * 128;        // 64

    int tid = threadIdx.x;
    size_t m0 = (size_t)blockIdx.x * 64;
    if (tid < 64) ss[tid] = speed[m0 + tid];
    __syncthreads();
#pragma unroll
    for (int t = 0; t < 32; t++) {
        int e = tid + t * 256;
        int s = e >> 7, k = e & 127;
        h1[s * 132 + k] = fmaxf(ss[s] * W1[k] + b1[k], 0.f);
    }
    __syncthreads();
    gemm64x128<true >(h1, 132, 128, W2, 128, 0, b2, h2, 132, 0, 0, Ws);
    gemm64x128<false>(h2, 132, 128, W3, 128, 0, b3, g_v, 128, m0, 0, Ws);
}

// ---------------- join: [p_i | v] [64,640] @ join_W [640,512] ----------------
// grid: (B/64, 4). smem: Xs[64][644], Ws[32*128]
__global__ void k_join(const float* __restrict__ p_i,
                       const float* __restrict__ jW, const float* __restrict__ jb)
{
    extern __shared__ float sm[];
    float* Xs = sm;                   // 64*644
    float* Ws = Xs + 64 * 644;        // 32*128

    int tid = threadIdx.x;
    size_t m0 = (size_t)blockIdx.x * 64;
    int n0 = blockIdx.y * 128;

#pragma unroll
    for (int t = 0; t < 32; t++) {    // p_i tile: 64*512 floats
        int off = (tid + t * 256) * 4;
        int s = off >> 9, k = off & 511;
        *(float4*)(Xs + s * 644 + k) = *(const float4*)(p_i + m0 * 512 + off);
    }
#pragma unroll
    for (int t = 0; t < 8; t++) {     // v tile: 64*128 floats
        int off = (tid + t * 256) * 4;
        int s = off >> 7, k = off & 127;
        *(float4*)(Xs + s * 644 + 512 + k) = *(const float4*)(g_v + m0 * 128 + off);
    }
    __syncthreads();
    gemm64x128<false>(Xs, 644, 640, jW, 512, n0, jb, g_joined, 512, m0, n0, Ws);
}

// ---------------- speed-pred MLP: 512 -> 128 -> 128 -> 1 ----------------
// smem: Xs[64][516] (reused as Y2[64][132]), Y1[64][132], Ws[32*128], w3s[128]
__global__ void k_vp(const float* __restrict__ p_i,
                     const float* __restrict__ W1, const float* __restrict__ b1,
                     const float* __restrict__ W2, const float* __restrict__ b2,
                     const float* __restrict__ W3, const float* __restrict__ b3,
                     float* __restrict__ out)
{
    extern __shared__ float sm[];
    float* Xs = sm;                   // 64*516
    float* Y1 = Xs + 64 * 516;        // 64*132
    float* Ws = Y1 + 64 * 132;        // 32*128
    float* w3s = Ws + 32 * 128;       // 128

    int tid = threadIdx.x;
    size_t m0 = (size_t)blockIdx.x * 64;
#pragma unroll
    for (int t = 0; t < 32; t++) {
        int off = (tid + t * 256) * 4;
        int s = off >> 9, k = off & 511;
        *(float4*)(Xs + s * 516 + k) = *(const float4*)(p_i + m0 * 512 + off);
    }
    if (tid < 128) w3s[tid] = W3[tid];
    __syncthreads();
    gemm64x128<true>(Xs, 516, 512, W1, 128, 0, b1, Y1, 132, 0, 0, Ws);
    float* Y2 = Xs;  // overlay (Xs dead after layer 1)
    gemm64x128<true>(Y1, 132, 128, W2, 128, 0, b2, Y2, 132, 0, 0, Ws);
    __syncthreads();
    if (tid < 64) {
        float sum = b3[0];
        const float* yr = Y2 + tid * 132;
#pragma unroll 8
        for (int k = 0; k < 128; k++) sum += yr[k] * w3s[k];
        out[m0 + tid] = sum;
    }
}

// ---------------- routed control heads: 512 -> 256 -> 256 -> 3 ----------------
// grid: 516 blocks over 64-aligned expert segments.
// smem: Xs[64][516] (reused as Y2[64][260]), Y1[64][260], Ws[32*128], w3s[768], ridx[64]
__global__ void k_ctrl(const float* __restrict__ W1, const float* __restrict__ b1,
                       const float* __restrict__ W2, const float* __restrict__ b2,
                       const float* __restrict__ W3, const float* __restrict__ b3,
                       float* __restrict__ out)
{
    extern __shared__ float sm[];
    float* Xs  = sm;                   // 64*516
    float* Y1  = Xs + 64 * 516;        // 64*260
    float* Ws  = Y1 + 64 * 260;        // 32*128
    float* w3s = Ws + 32 * 128;        // 768
    int*   ridx = (int*)(w3s + 768);   // 64

    int tid = threadIdx.x;
    int p0 = blockIdx.x * 64;

    int s1 = g_seg[1], s2 = g_seg[2], s3 = g_seg[3], s4 = g_seg[4];
    if (p0 >= s4) return;
    int e, segb;
    if (p0 < s1)      { e = 0; segb = g_seg[0]; }
    else if (p0 < s2) { e = 1; segb = s1; }
    else if (p0 < s3) { e = 2; segb = s2; }
    else              { e = 3; segb = s3; }
    int cnt = g_cnt[e];

    if (tid < 64) {
        int local = p0 - segb + tid;
        ridx[tid] = (local < cnt) ? g_idx[p0 + tid] : -1;
    }
    w3s[tid]       = W3[e * 768 + tid];
    w3s[256 + tid] = W3[e * 768 + 256 + tid];
    w3s[512 + tid] = W3[e * 768 + 512 + tid];
    __syncthreads();

    // gather joined rows
#pragma unroll
    for (int t = 0; t < 32; t++) {
        int off = (tid + t * 256) * 4;
        int s = off >> 9, k = off & 511;
        int r = ridx[s];
        if (r < 0) r = 0;
        *(float4*)(Xs + s * 516 + k) = *(const float4*)(g_joined + (size_t)r * 512 + k);
    }
    __syncthreads();

    const float* W1e = W1 + (size_t)e * 512 * 256;
    const float* b1e = b1 + e * 256;
    gemm64x128<true>(Xs, 516, 512, W1e, 256, 0,   b1e, Y1, 260, 0, 0,   Ws);
    gemm64x128<true>(Xs, 516, 512, W1e, 256, 128, b1e, Y1, 260, 0, 128, Ws);

    float* Y2 = Xs;  // overlay (Xs dead after layer 1)
    const float* W2e = W2 + (size_t)e * 256 * 256;
    const float* b2e = b2 + e * 256;
    gemm64x128<true>(Y1, 260, 256, W2e, 256, 0,   b2e, Y2, 260, 0, 0,   Ws);
    gemm64x128<true>(Y1, 260, 256, W2e, 256, 128, b2e, Y2, 260, 0, 128, Ws);
    __syncthreads();

    if (tid < 192) {
        int s = tid / 3, j = tid % 3;
        int r = ridx[s];
        if (r >= 0) {
            float sum = b3[e * 3 + j];
            const float* yr = Y2 + s * 260;
#pragma unroll 8
            for (int k = 0; k < 256; k++) sum += yr[k] * w3s[k * 3 + j];
            out[(size_t)B_TOT + (size_t)r * 3 + j] = sum;
        }
    }
}

// ---------------- launcher ----------------
#define SP_SMEM   ((64*132*2 + 32*128 + 64) * 4)
#define JOIN_SMEM ((64*644 + 32*128) * 4)
#define VP_SMEM   ((64*516 + 64*132 + 32*128 + 128) * 4)
#define CTRL_SMEM ((64*516 + 64*260 + 32*128 + 768 + 64) * 4)

extern "C" void kernel_launch(void* const* d_in, const int* in_sizes, int n_in,
                              void* d_out, int out_size)
{
    const float* p_i    = (const float*)d_in[0];
    const float* speed  = (const float*)d_in[1];
    const int*   cmd    = (const int*)d_in[2];
    const float* sp_W1  = (const float*)d_in[3];
    const float* sp_b1  = (const float*)d_in[4];
    const float* sp_W2  = (const float*)d_in[5];
    const float* sp_b2  = (const float*)d_in[6];
    const float* sp_W3  = (const float*)d_in[7];
    const float* sp_b3  = (const float*)d_in[8];
    const float* vp_W1  = (const float*)d_in[9];
    const float* vp_b1  = (const float*)d_in[10];
    const float* vp_W2  = (const float*)d_in[11];
    const float* vp_b2  = (const float*)d_in[12];
    const float* vp_W3  = (const float*)d_in[13];
    const float* vp_b3  = (const float*)d_in[14];
    const float* join_W = (const float*)d_in[15];
    const float* join_b = (const float*)d_in[16];
    const float* c_W1   = (const float*)d_in[17];
    const float* c_b1   = (const float*)d_in[18];
    const float* c_W2   = (const float*)d_in[19];
    const float* c_b2   = (const float*)d_in[20];
    const float* c_W3   = (const float*)d_in[21];
    const float* c_b3   = (const float*)d_in[22];
    float* out = (float*)d_out;

    cudaFuncSetAttribute(k_sp,   cudaFuncAttributeMaxDynamicSharedMemorySize, SP_SMEM);
    cudaFuncSetAttribute(k_join, cudaFuncAttributeMaxDynamicSharedMemorySize, JOIN_SMEM);
    cudaFuncSetAttribute(k_vp,   cudaFuncAttributeMaxDynamicSharedMemorySize, VP_SMEM);
    cudaFuncSetAttribute(k_ctrl, cudaFuncAttributeMaxDynamicSharedMemorySize, CTRL_SMEM);

    // routing
    k_reset<<<1, 32>>>();
    k_count<<<B_TOT / 256, 256>>>(cmd);
    k_seg<<<1, 32>>>();
    k_scatter<<<B_TOT / 256, 256>>>(cmd);

    // compute
    k_sp<<<B_TOT / 64, 256, SP_SMEM>>>(speed, sp_W1, sp_b1, sp_W2, sp_b2, sp_W3, sp_b3);
    dim3 jg(B_TOT / 64, 4);
    k_join<<<jg, 256, JOIN_SMEM>>>(p_i, join_W, join_b);
    k_vp<<<B_TOT / 64, 256, VP_SMEM>>>(p_i, vp_W1, vp_b1, vp_W2, vp_b2, vp_W3, vp_b3, out);
    k_ctrl<<<(B_TOT / 64) + 4, 256, CTRL_SMEM>>>(c_W1, c_b1, c_W2, c_b2, c_W3, c_b3, out);
}